// round 9
// baseline (speedup 1.0000x reference)
#include <cuda_runtime.h>
#include <cuda_bf16.h>

// Problem constants
#define BSZ 64
#define KREG 19
#define KALL 20          // 19 regions + 1 global (all-ones weight row)
#define CCH 384
#define PPIX 256         // 16x16
#define DOUT 256
#define NROWS (BSZ * KALL)   // 1280

// Scratch (device globals; no allocation allowed)
__device__ float g_wsmall[BSZ * KALL * PPIX];     // [b][k][p]
__device__ float g_allfeats[NROWS * CCH];         // [row][c]
__device__ float g_Wt[CCH * DOUT];                // [c][d]

typedef unsigned long long ull;

// ---- packed f32x2 helpers (Blackwell) --------------------------------------
__device__ __forceinline__ ull pack2(float lo, float hi) {
    ull r;
    asm("mov.b64 %0, {%1, %2};" : "=l"(r) : "f"(lo), "f"(hi));
    return r;
}
__device__ __forceinline__ void unpack2(ull v, float& lo, float& hi) {
    asm("mov.b64 {%0, %1}, %2;" : "=f"(lo), "=f"(hi) : "l"(v));
}
__device__ __forceinline__ ull ffma2(ull a, ull b, ull c) {
    ull d;
    asm("fma.rn.f32x2 %0, %1, %2, %3;" : "=l"(d) : "l"(a), "l"(b), "l"(c));
    return d;
}

// ---------------------------------------------------------------------------
// kA: merged prep kernel (R5 proven config: 2 tiles/block, 712 blocks).
//  blocks [0,608):    downsample, TWO (b,k) region tiles per block
//  blocks [608,704):  W transpose -> g_Wt [c][d]
//  blocks [704,712):  all-ones rows (k=19)
// Downsample: out(i,j) = 0.25*(s[16i+7][16j+7]+s[16i+7][16j+8]
//                             +s[16i+8][16j+7]+s[16i+8][16j+8])
// ---------------------------------------------------------------------------
__global__ __launch_bounds__(256)
void kA_prep(const float* __restrict__ seg, const float* __restrict__ W) {
    int bx = blockIdx.x;
    int t = threadIdx.x;

    if (bx < 608) {
        __shared__ float smk[2][32 * 34];
        int r = t >> 3;              // 0..31 smem row
        int lane8 = t & 7;
        int gi = r >> 1;
        int grow = 16 * gi + 7 + (r & 1);

        float4 v[2][4];
#pragma unroll
        for (int s2 = 0; s2 < 2; s2++) {
            int rk = bx * 2 + s2;               // 0..1215
            const float4* row4 = reinterpret_cast<const float4*>(
                seg + ((size_t)rk * 256 + grow) * 256);
#pragma unroll
            for (int u = 0; u < 4; u++) {
                int s = lane8 + 8 * u;
                int f = 4 * (s >> 1) + 1 + (s & 1);
                v[s2][u] = row4[f];
            }
        }
#pragma unroll
        for (int s2 = 0; s2 < 2; s2++)
#pragma unroll
            for (int u = 0; u < 4; u++) {
                int s = lane8 + 8 * u;
                smk[s2][r * 34 + s] = (s & 1) ? v[s2][u].x : v[s2][u].w;
            }
        __syncthreads();

        int i = t >> 4, j = t & 15;
#pragma unroll
        for (int s2 = 0; s2 < 2; s2++) {
            int rk = bx * 2 + s2;
            int b = rk / KREG, k = rk - b * KREG;
            const float2* lo2 = reinterpret_cast<const float2*>(
                smk[s2] + (2 * i) * 34 + 2 * j);
            const float2* hi2 = reinterpret_cast<const float2*>(
                smk[s2] + (2 * i + 1) * 34 + 2 * j);
            float2 a = *lo2, c = *hi2;
            g_wsmall[(b * KALL + k) * PPIX + t] = 0.25f * (a.x + a.y + c.x + c.y);
        }
    } else if (bx < 704) {
        __shared__ float ts[32][33];
        int id = bx - 608;            // 0..95
        int c0 = (id % 12) * 32;
        int d0 = (id / 12) * 32;
        int tx = t & 31, ty = t >> 5; // 32 x 8
#pragma unroll
        for (int i = 0; i < 4; i++)
            ts[ty + 8 * i][tx] = W[(d0 + ty + 8 * i) * CCH + c0 + tx];
        __syncthreads();
#pragma unroll
        for (int i = 0; i < 4; i++)
            g_Wt[(c0 + ty + 8 * i) * DOUT + d0 + tx] = ts[tx][ty + 8 * i];
    } else {
        // ones rows: 64 b x 256 p = 4096 float4
        int e4 = (bx - 704) * 512 + t;
#pragma unroll
        for (int it = 0; it < 2; it++, e4 += 256) {
            int b = e4 >> 6;               // 64 float4 per b
            int p4 = e4 & 63;
            float4* dst = reinterpret_cast<float4*>(
                g_wsmall + (b * KALL + KREG) * PPIX + p4 * 4);
            *dst = make_float4(1.f, 1.f, 1.f, 1.f);
        }
    }
}

// ---------------------------------------------------------------------------
// K2 (v1, from the 49.7us run): per-batch GEMM
//   A[b] = (1/256) * w[20 x 256] * F[b]^T[256 x 384]
// ---------------------------------------------------------------------------
__global__ void k2_region_gemm(const float* __restrict__ F) {
    __shared__ float ws[PPIX * KALL];   // [p][k], stride 20
    __shared__ float fs[32 * 129];      // [p][c], stride 129

    int b = blockIdx.x;
    int c0 = blockIdx.y * 128;
    int t = threadIdx.x;                // 256

    const float* wsm = g_wsmall + b * KALL * PPIX;
    for (int idx = t; idx < KALL * PPIX; idx += 256) {
        int k = idx >> 8, p = idx & 255;
        ws[p * KALL + k] = wsm[idx];
    }

    int cg = t & 63;
    int kg = t >> 6;
    float acc[5][2] = {};

    const float* Fb = F + ((size_t)b * CCH + c0) * PPIX;

    for (int pc = 0; pc < PPIX; pc += 32) {
        __syncthreads();
#pragma unroll
        for (int r = 0; r < 4; r++) {
            int linear = r * 256 + t;
            int c = linear >> 3;
            int p4 = linear & 7;
            float4 v = *reinterpret_cast<const float4*>(Fb + c * PPIX + pc + p4 * 4);
            int p = p4 * 4;
            fs[(p + 0) * 129 + c] = v.x;
            fs[(p + 1) * 129 + c] = v.y;
            fs[(p + 2) * 129 + c] = v.z;
            fs[(p + 3) * 129 + c] = v.w;
        }
        __syncthreads();

#pragma unroll 4
        for (int p = 0; p < 32; p++) {
            const float* wr = ws + (pc + p) * KALL + kg * 5;
            float f0 = fs[p * 129 + cg];
            float f1 = fs[p * 129 + 64 + cg];
#pragma unroll
            for (int i = 0; i < 5; i++) {
                float w = wr[i];
                acc[i][0] = fmaf(w, f0, acc[i][0]);
                acc[i][1] = fmaf(w, f1, acc[i][1]);
            }
        }
    }

    const float inv = 1.0f / 256.0f;
    float* A = g_allfeats + (size_t)(b * KALL) * CCH + c0;
#pragma unroll
    for (int i = 0; i < 5; i++) {
        int k = kg * 5 + i;
        A[k * CCH + cg]      = acc[i][0] * inv;
        A[k * CCH + 64 + cg] = acc[i][1] * inv;
    }
}

// ---------------------------------------------------------------------------
// K3 v4: single-pass projection  out = relu(A[1280x384] * Wt + bias)
//  grid (40 row-blocks, 4 d-splits of 64), 256 threads, full K=384.
//  Thread: 4 rows (2 packed pairs) x 2 d.  A staged [k][r] (pad 36) ->
//  broadcast LDS.128 gives 2 native row-pairs; W staged DUPLICATED
//  ([k][2d], pad 130) -> one LDS.64 per d.
//  Double-buffered chunks (32 k) with register prefetch.
// ---------------------------------------------------------------------------
#define K3_RB  32
#define K3_KC  32
#define K3_NCH (CCH / K3_KC)     // 12

__global__ __launch_bounds__(256)
void k3_project(const float* __restrict__ bias, float* __restrict__ out) {
    __shared__ float asf[2][K3_KC * 36];       // [buf][kk][r(pad 36)]
    __shared__ float wdup[2][K3_KC * 130];     // [buf][kk][2d dup(pad 130)]

    int t = threadIdx.x;
    int rg = t >> 5;            // 0..7 -> rows rg*4 .. rg*4+3
    int dg = t & 31;            // d in {dg, dg+32} of this 64-d tile
    int row0 = blockIdx.x * K3_RB;
    int d0 = blockIdx.y * 64;

    int ar = t >> 3;            // A: row index 0..31
    int aq = t & 7;             // A: k-quad 0..7
    int wk = t >> 4;            // W: kk 0..15 (+16 on second pass)
    int wc = t & 15;            // W: float4 index within 64-d row

    const float* Ab = g_allfeats + (size_t)row0 * CCH;
    const float* Wb = g_Wt + d0;

    float4 pa, pw0, pw1;
    pa  = *reinterpret_cast<const float4*>(Ab + ar * CCH + aq * 4);
    pw0 = *reinterpret_cast<const float4*>(Wb + (size_t)wk * DOUT + wc * 4);
    pw1 = *reinterpret_cast<const float4*>(Wb + (size_t)(wk + 16) * DOUT + wc * 4);

    ull acc00 = 0, acc01 = 0, acc10 = 0, acc11 = 0;

    for (int ch = 0; ch < K3_NCH; ch++) {
        int buf = ch & 1;
        {
            float* as = asf[buf];
            as[(4 * aq + 0) * 36 + ar] = pa.x;
            as[(4 * aq + 1) * 36 + ar] = pa.y;
            as[(4 * aq + 2) * 36 + ar] = pa.z;
            as[(4 * aq + 3) * 36 + ar] = pa.w;
            float* wd = wdup[buf];
            float2* w2p;
            w2p = reinterpret_cast<float2*>(wd + wk * 130 + 2 * (4 * wc));
            w2p[0] = make_float2(pw0.x, pw0.x);
            w2p[1] = make_float2(pw0.y, pw0.y);
            w2p[2] = make_float2(pw0.z, pw0.z);
            w2p[3] = make_float2(pw0.w, pw0.w);
            w2p = reinterpret_cast<float2*>(wd + (wk + 16) * 130 + 2 * (4 * wc));
            w2p[0] = make_float2(pw1.x, pw1.x);
            w2p[1] = make_float2(pw1.y, pw1.y);
            w2p[2] = make_float2(pw1.z, pw1.z);
            w2p[3] = make_float2(pw1.w, pw1.w);
        }
        __syncthreads();

        if (ch + 1 < K3_NCH) {
            int kb = (ch + 1) * K3_KC;
            pa  = *reinterpret_cast<const float4*>(Ab + ar * CCH + kb + aq * 4);
            pw0 = *reinterpret_cast<const float4*>(Wb + (size_t)(kb + wk) * DOUT + wc * 4);
            pw1 = *reinterpret_cast<const float4*>(Wb + (size_t)(kb + wk + 16) * DOUT + wc * 4);
        }

        const float* as = asf[buf];
        const float* wd = wdup[buf];
#pragma unroll
        for (int kk = 0; kk < K3_KC; kk++) {
            ulonglong2 a2 = *reinterpret_cast<const ulonglong2*>(as + kk * 36 + rg * 4);
            ull w0 = *reinterpret_cast<const ull*>(wd + kk * 130 + 2 * dg);
            ull w1 = *reinterpret_cast<const ull*>(wd + kk * 130 + 2 * (dg + 32));
            acc00 = ffma2(a2.x, w0, acc00);
            acc01 = ffma2(a2.x, w1, acc01);
            acc10 = ffma2(a2.y, w0, acc10);
            acc11 = ffma2(a2.y, w1, acc11);
        }
        __syncthreads();
    }

    float b0 = bias[d0 + dg];
    float b1 = bias[d0 + dg + 32];
    float v00, v01, v10, v11, v20, v21, v30, v31;
    unpack2(acc00, v00, v10);
    unpack2(acc01, v01, v11);
    unpack2(acc10, v20, v30);
    unpack2(acc11, v21, v31);

    int r = row0 + rg * 4;
    float* o0 = out + (size_t)r * DOUT + d0;
    o0[dg]                 = fmaxf(v00 + b0, 0.0f);
    o0[dg + 32]            = fmaxf(v01 + b1, 0.0f);
    o0[DOUT + dg]          = fmaxf(v10 + b0, 0.0f);
    o0[DOUT + dg + 32]     = fmaxf(v11 + b1, 0.0f);
    o0[2 * DOUT + dg]      = fmaxf(v20 + b0, 0.0f);
    o0[2 * DOUT + dg + 32] = fmaxf(v21 + b1, 0.0f);
    o0[3 * DOUT + dg]      = fmaxf(v30 + b0, 0.0f);
    o0[3 * DOUT + dg + 32] = fmaxf(v31 + b1, 0.0f);
}

// ---------------------------------------------------------------------------
extern "C" void kernel_launch(void* const* d_in, const int* in_sizes, int n_in,
                              void* d_out, int out_size) {
    const float* F    = (const float*)d_in[0];   // [64,384,16,16]
    const float* seg  = (const float*)d_in[1];   // [64,19,256,256]
    const float* W    = (const float*)d_in[2];   // [256,384]
    const float* bias = (const float*)d_in[3];   // [256]
    float* out = (float*)d_out;                  // [64, 5120]

    kA_prep<<<712, 256>>>(seg, W);
    k2_region_gemm<<<dim3(BSZ, 3), 256>>>(F);
    k3_project<<<dim3(40, 4), 256>>>(bias, out);
}

// round 12
// speedup vs baseline: 1.5838x; 1.5838x over previous
#include <cuda_runtime.h>
#include <cuda_bf16.h>

// Problem constants
#define BSZ 64
#define KREG 19
#define KALL 20          // 19 regions + 1 global (all-ones weight row)
#define CCH 384
#define PPIX 256         // 16x16
#define DOUT 256
#define NROWS (BSZ * KALL)   // 1280

// Scratch (device globals; no allocation allowed)
__device__ float g_wsmall[BSZ * KALL * PPIX];     // [b][k][p]
__device__ float g_allfeats[NROWS * CCH];         // [row][c]
__device__ float g_Wt[CCH * DOUT];                // [c][d]

typedef unsigned long long ull;

// ---- packed f32x2 helpers (Blackwell) --------------------------------------
__device__ __forceinline__ ull pack2(float lo, float hi) {
    ull r;
    asm("mov.b64 %0, {%1, %2};" : "=l"(r) : "f"(lo), "f"(hi));
    return r;
}
__device__ __forceinline__ void unpack2(ull v, float& lo, float& hi) {
    asm("mov.b64 {%0, %1}, %2;" : "=f"(lo), "=f"(hi) : "l"(v));
}
__device__ __forceinline__ ull ffma2(ull a, ull b, ull c) {
    ull d;
    asm("fma.rn.f32x2 %0, %1, %2, %3;" : "=l"(d) : "l"(a), "l"(b), "l"(c));
    return d;
}

// ---------------------------------------------------------------------------
// kA: merged prep kernel (measured 11.7us config: 2 tiles/block).
//  blocks [0,608):    downsample, TWO (b,k) region tiles per block
//  blocks [608,704):  W transpose -> g_Wt [c][d]
//  blocks [704,712):  all-ones rows (k=19)
// ---------------------------------------------------------------------------
__global__ __launch_bounds__(256)
void kA_prep(const float* __restrict__ seg, const float* __restrict__ W) {
    int bx = blockIdx.x;
    int t = threadIdx.x;

    if (bx < 608) {
        __shared__ float smk[2][32 * 34];
        int r = t >> 3;
        int lane8 = t & 7;
        int gi = r >> 1;
        int grow = 16 * gi + 7 + (r & 1);

        float4 v[2][4];
#pragma unroll
        for (int s2 = 0; s2 < 2; s2++) {
            int rk = bx * 2 + s2;               // 0..1215
            const float4* row4 = reinterpret_cast<const float4*>(
                seg + ((size_t)rk * 256 + grow) * 256);
#pragma unroll
            for (int u = 0; u < 4; u++) {
                int s = lane8 + 8 * u;
                int f = 4 * (s >> 1) + 1 + (s & 1);
                v[s2][u] = row4[f];
            }
        }
#pragma unroll
        for (int s2 = 0; s2 < 2; s2++)
#pragma unroll
            for (int u = 0; u < 4; u++) {
                int s = lane8 + 8 * u;
                smk[s2][r * 34 + s] = (s & 1) ? v[s2][u].x : v[s2][u].w;
            }
        __syncthreads();

        int i = t >> 4, j = t & 15;
#pragma unroll
        for (int s2 = 0; s2 < 2; s2++) {
            int rk = bx * 2 + s2;
            int b = rk / KREG, k = rk - b * KREG;
            const float2* lo2 = reinterpret_cast<const float2*>(
                smk[s2] + (2 * i) * 34 + 2 * j);
            const float2* hi2 = reinterpret_cast<const float2*>(
                smk[s2] + (2 * i + 1) * 34 + 2 * j);
            float2 a = *lo2, c = *hi2;
            g_wsmall[(b * KALL + k) * PPIX + t] = 0.25f * (a.x + a.y + c.x + c.y);
        }
    } else if (bx < 704) {
        __shared__ float ts[32][33];
        int id = bx - 608;
        int c0 = (id % 12) * 32;
        int d0 = (id / 12) * 32;
        int tx = t & 31, ty = t >> 5;
#pragma unroll
        for (int i = 0; i < 4; i++)
            ts[ty + 8 * i][tx] = W[(d0 + ty + 8 * i) * CCH + c0 + tx];
        __syncthreads();
#pragma unroll
        for (int i = 0; i < 4; i++)
            g_Wt[(c0 + ty + 8 * i) * DOUT + d0 + tx] = ts[tx][ty + 8 * i];
    } else {
        int e4 = (bx - 704) * 512 + t;
#pragma unroll
        for (int it = 0; it < 2; it++, e4 += 256) {
            int b = e4 >> 6;
            int p4 = e4 & 63;
            float4* dst = reinterpret_cast<float4*>(
                g_wsmall + (b * KALL + KREG) * PPIX + p4 * 4);
            *dst = make_float4(1.f, 1.f, 1.f, 1.f);
        }
    }
}

// ---------------------------------------------------------------------------
// K2 v2 (measured ~5.2us): per-batch GEMM
//   A[b] = (1/256) * w[20 x 256] * F[b]^T[256 x 384]
// ---------------------------------------------------------------------------
__global__ __launch_bounds__(256)
void k2_region_gemm(const float* __restrict__ F) {
    __shared__ float sm[10240];           // 40 KB
    float* ws = sm;                       // [p][k] 256*20 = 5120 floats
    float* fs = sm + 5120;                // [32 p][130] = 4160 floats
    float2* red = reinterpret_cast<float2*>(sm);  // [4][1280] float2 (reuse)

    int b = blockIdx.x;
    int c0 = blockIdx.y * 128;
    int t = threadIdx.x;
    int pg = t >> 6;
    int cgp = t & 63;

    const float* wsm = g_wsmall + b * KALL * PPIX;
    for (int idx = t; idx < KALL * PPIX; idx += 256) {
        int k = idx >> 8, p = idx & 255;
        ws[p * KALL + k] = wsm[idx];
    }

    const float* Fb = F + ((size_t)b * CCH + c0) * PPIX;

    float4 pf[4];
#pragma unroll
    for (int r = 0; r < 4; r++) {
        int linear = r * 256 + t;
        int c = linear >> 3;
        int p4 = linear & 7;
        pf[r] = *reinterpret_cast<const float4*>(Fb + c * PPIX + p4 * 4);
    }

    ull acc[10][2];
#pragma unroll
    for (int i = 0; i < 10; i++) { acc[i][0] = 0ull; acc[i][1] = 0ull; }

    for (int ch = 0; ch < 8; ch++) {
        if (ch) __syncthreads();
#pragma unroll
        for (int r = 0; r < 4; r++) {
            int linear = r * 256 + t;
            int c = linear >> 3;
            int p4 = linear & 7;
            fs[(p4 * 4 + 0) * 130 + c] = pf[r].x;
            fs[(p4 * 4 + 1) * 130 + c] = pf[r].y;
            fs[(p4 * 4 + 2) * 130 + c] = pf[r].z;
            fs[(p4 * 4 + 3) * 130 + c] = pf[r].w;
        }
        __syncthreads();
        if (ch < 7) {
#pragma unroll
            for (int r = 0; r < 4; r++) {
                int linear = r * 256 + t;
                int c = linear >> 3;
                int p4 = linear & 7;
                pf[r] = *reinterpret_cast<const float4*>(
                    Fb + c * PPIX + (ch + 1) * 32 + p4 * 4);
            }
        }

        int pc = ch * 32;
#pragma unroll
        for (int pp = 0; pp < 8; pp++) {
            int pl = pg * 8 + pp;
            const float* wr = ws + (pc + pl) * KALL;
            ull f2 = *reinterpret_cast<const ull*>(fs + pl * 130 + 2 * cgp);
            float f0, f1;
            unpack2(f2, f0, f1);
            ull fd0 = pack2(f0, f0);
            ull fd1 = pack2(f1, f1);
#pragma unroll
            for (int ki = 0; ki < 10; ki++) {
                ull w2 = *reinterpret_cast<const ull*>(wr + 2 * ki);
                acc[ki][0] = ffma2(w2, fd0, acc[ki][0]);
                acc[ki][1] = ffma2(w2, fd1, acc[ki][1]);
            }
        }
    }

    __syncthreads();
#pragma unroll
    for (int ki = 0; ki < 10; ki++) {
#pragma unroll
        for (int cc = 0; cc < 2; cc++) {
            float lo, hi;
            unpack2(acc[ki][cc], lo, hi);
            red[pg * 1280 + ki * 128 + 2 * cgp + cc] = make_float2(lo, hi);
        }
    }
    __syncthreads();

    const float inv = 1.0f / 256.0f;
    float* A = g_allfeats + (size_t)(b * KALL) * CCH + c0;
#pragma unroll
    for (int j = 0; j < 5; j++) {
        int i = t + 256 * j;
        float2 s0 = red[i];
        float2 s1 = red[1280 + i];
        float2 s2 = red[2560 + i];
        float2 s3 = red[3840 + i];
        float lo = (s0.x + s1.x) + (s2.x + s3.x);
        float hi = (s0.y + s1.y) + (s2.y + s3.y);
        int kp = i >> 7;
        int col = i & 127;
        A[(2 * kp) * CCH + col]     = lo * inv;
        A[(2 * kp + 1) * CCH + col] = hi * inv;
    }
}

// ---------------------------------------------------------------------------
// K3 v5: projection in the k2v2 template.
//   out[1280 x 256] = relu(A[1280 x 384] * Wt[384 x 256] + bias)
//  grid (128 rowgroups of 10, 2 d-halves of 128), 256 threads.
//  4 k-groups x 64 d-pair threads; thread: 5 row-pairs x 1 d-pair over its
//  96 k's. Row-pairs are broadcast LDS.64 from A-transposed; Wt chunk staged
//  [k][132] -> spread LDS.64 per d-pair. Register-prefetch staging; smem
//  tree-reduce over k-groups; bias+relu fused.
// ---------------------------------------------------------------------------
__global__ __launch_bounds__(256)
void k3_project(const float* __restrict__ bias, float* __restrict__ out) {
    __shared__ float sm[8064];            // 31.5 KB
    float* as = sm;                       // [k=384][r=10] = 3840 floats
    float* fs = sm + 3840;                // [32 k][132] = 4224 floats
    float2* red = reinterpret_cast<float2*>(sm);  // [4][640] float2 (reuse)

    int t = threadIdx.x;
    int g = t >> 6;                       // k-group 0..3
    int dp = t & 63;                      // d-pair: d = d0 + 2dp + {0,1}
    int row0 = blockIdx.x * 10;
    int d0 = blockIdx.y * 128;

    // stage A transposed: as[k*10 + r] = A[row0+r][k]
    const float* Ar = g_allfeats + (size_t)row0 * CCH;
#pragma unroll
    for (int i = 0; i < 15; i++) {
        int idx = i * 256 + t;            // 3840 = 15*256
        int r = idx / CCH;
        int k = idx - r * CCH;
        as[k * 10 + r] = Ar[idx];
    }

    const float* Wb = g_Wt + d0;

    // prefetch Wt chunk 0 (32 k x 128 d = 1024 float4, 4/thread)
    float4 pf[4];
#pragma unroll
    for (int i = 0; i < 4; i++) {
        int linear = i * 256 + t;
        int k = linear >> 5;              // 32 f4 per k-row
        int c4 = linear & 31;
        pf[i] = *reinterpret_cast<const float4*>(Wb + (size_t)k * DOUT + c4 * 4);
    }

    ull acc[5][2];
#pragma unroll
    for (int i = 0; i < 5; i++) { acc[i][0] = 0ull; acc[i][1] = 0ull; }

    for (int ch = 0; ch < 12; ch++) {
        if (ch) __syncthreads();          // prior chunk's reads complete
#pragma unroll
        for (int i = 0; i < 4; i++) {
            int linear = i * 256 + t;
            int k = linear >> 5;
            int c4 = linear & 31;
            *reinterpret_cast<float4*>(fs + k * 132 + c4 * 4) = pf[i];
        }
        __syncthreads();                  // fs (and as on ch=0) visible
        if (ch < 11) {
#pragma unroll
            for (int i = 0; i < 4; i++) {
                int linear = i * 256 + t;
                int k = linear >> 5;
                int c4 = linear & 31;
                pf[i] = *reinterpret_cast<const float4*>(
                    Wb + (size_t)((ch + 1) * 32 + k) * DOUT + c4 * 4);
            }
        }

        int kbase = ch * 32;
#pragma unroll
        for (int j = 0; j < 8; j++) {
            int kk = g * 8 + j;           // k within chunk
            int k = kbase + kk;
            ull w2 = *reinterpret_cast<const ull*>(fs + kk * 132 + 2 * dp);
            float w0, w1;
            unpack2(w2, w0, w1);
            ull wd0 = pack2(w0, w0);
            ull wd1 = pack2(w1, w1);
            const float* arow = as + k * 10;
#pragma unroll
            for (int ri = 0; ri < 5; ri++) {
                ull a2 = *reinterpret_cast<const ull*>(arow + 2 * ri);  // broadcast
                acc[ri][0] = ffma2(a2, wd0, acc[ri][0]);
                acc[ri][1] = ffma2(a2, wd1, acc[ri][1]);
            }
        }
    }

    // tree reduce over 4 k-groups (red overlays as/fs)
    __syncthreads();
#pragma unroll
    for (int ri = 0; ri < 5; ri++) {
#pragma unroll
        for (int cc = 0; cc < 2; cc++) {
            float lo, hi;
            unpack2(acc[ri][cc], lo, hi);
            red[g * 640 + dp * 10 + ri * 2 + cc] = make_float2(lo, hi);
        }
    }
    __syncthreads();

    for (int idx = t; idx < 640; idx += 256) {
        float2 s0 = red[idx];
        float2 s1 = red[640 + idx];
        float2 s2 = red[1280 + idx];
        float2 s3 = red[1920 + idx];
        float lo = (s0.x + s1.x) + (s2.x + s3.x);
        float hi = (s0.y + s1.y) + (s2.y + s3.y);
        int dpi = idx / 10;
        int rem = idx - dpi * 10;
        int ri = rem >> 1;
        int cc = rem & 1;
        int d = d0 + 2 * dpi + cc;
        float bv = bias[d];
        out[(size_t)(row0 + 2 * ri) * DOUT + d]     = fmaxf(lo + bv, 0.0f);
        out[(size_t)(row0 + 2 * ri + 1) * DOUT + d] = fmaxf(hi + bv, 0.0f);
    }
}

// ---------------------------------------------------------------------------
extern "C" void kernel_launch(void* const* d_in, const int* in_sizes, int n_in,
                              void* d_out, int out_size) {
    const float* F    = (const float*)d_in[0];   // [64,384,16,16]
    const float* seg  = (const float*)d_in[1];   // [64,19,256,256]
    const float* W    = (const float*)d_in[2];   // [256,384]
    const float* bias = (const float*)d_in[3];   // [256]
    float* out = (float*)d_out;                  // [64, 5120]

    kA_prep<<<712, 256>>>(seg, W);
    k2_region_gemm<<<dim3(BSZ, 3), 256>>>(F);
    k3_project<<<dim3(128, 2), 256>>>(bias, out);
}

// round 16
// speedup vs baseline: 1.5890x; 1.0033x over previous
#include <cuda_runtime.h>
#include <cuda_bf16.h>

// Problem constants
#define BSZ 64
#define KREG 19
#define KALL 20          // 19 regions + 1 global (all-ones weight row)
#define CCH 384
#define PPIX 256         // 16x16
#define DOUT 256
#define NROWS (BSZ * KALL)   // 1280

// Scratch (device globals; no allocation allowed)
__device__ float g_wsmall[BSZ * KALL * PPIX];     // [b][k][p]
__device__ float g_allfeats[NROWS * CCH];         // [row][c]
__device__ float g_Wt[CCH * DOUT];                // [c][d]

typedef unsigned long long ull;

// ---- packed f32x2 helpers (Blackwell) --------------------------------------
__device__ __forceinline__ ull pack2(float lo, float hi) {
    ull r;
    asm("mov.b64 %0, {%1, %2};" : "=l"(r) : "f"(lo), "f"(hi));
    return r;
}
__device__ __forceinline__ void unpack2(ull v, float& lo, float& hi) {
    asm("mov.b64 {%0, %1}, %2;" : "=f"(lo), "=f"(hi) : "l"(v));
}
__device__ __forceinline__ ull ffma2(ull a, ull b, ull c) {
    ull d;
    asm("fma.rn.f32x2 %0, %1, %2, %3;" : "=l"(d) : "l"(a), "l"(b), "l"(c));
    return d;
}

// ---------------------------------------------------------------------------
// kA: merged prep kernel (measured ~12us config: 2 tiles/block).
//  blocks [0,608):    downsample, TWO (b,k) region tiles per block
//  blocks [608,704):  W transpose -> g_Wt [c][d]
//  blocks [704,712):  all-ones rows (k=19)
// ---------------------------------------------------------------------------
__global__ __launch_bounds__(256)
void kA_prep(const float* __restrict__ seg, const float* __restrict__ W) {
    int bx = blockIdx.x;
    int t = threadIdx.x;

    if (bx < 608) {
        __shared__ float smk[2][32 * 34];
        int r = t >> 3;
        int lane8 = t & 7;
        int gi = r >> 1;
        int grow = 16 * gi + 7 + (r & 1);

        float4 v[2][4];
#pragma unroll
        for (int s2 = 0; s2 < 2; s2++) {
            int rk = bx * 2 + s2;               // 0..1215
            const float4* row4 = reinterpret_cast<const float4*>(
                seg + ((size_t)rk * 256 + grow) * 256);
#pragma unroll
            for (int u = 0; u < 4; u++) {
                int s = lane8 + 8 * u;
                int f = 4 * (s >> 1) + 1 + (s & 1);
                v[s2][u] = row4[f];
            }
        }
#pragma unroll
        for (int s2 = 0; s2 < 2; s2++)
#pragma unroll
            for (int u = 0; u < 4; u++) {
                int s = lane8 + 8 * u;
                smk[s2][r * 34 + s] = (s & 1) ? v[s2][u].x : v[s2][u].w;
            }
        __syncthreads();

        int i = t >> 4, j = t & 15;
#pragma unroll
        for (int s2 = 0; s2 < 2; s2++) {
            int rk = bx * 2 + s2;
            int b = rk / KREG, k = rk - b * KREG;
            const float2* lo2 = reinterpret_cast<const float2*>(
                smk[s2] + (2 * i) * 34 + 2 * j);
            const float2* hi2 = reinterpret_cast<const float2*>(
                smk[s2] + (2 * i + 1) * 34 + 2 * j);
            float2 a = *lo2, c = *hi2;
            g_wsmall[(b * KALL + k) * PPIX + t] = 0.25f * (a.x + a.y + c.x + c.y);
        }
    } else if (bx < 704) {
        __shared__ float ts[32][33];
        int id = bx - 608;
        int c0 = (id % 12) * 32;
        int d0 = (id / 12) * 32;
        int tx = t & 31, ty = t >> 5;
#pragma unroll
        for (int i = 0; i < 4; i++)
            ts[ty + 8 * i][tx] = W[(d0 + ty + 8 * i) * CCH + c0 + tx];
        __syncthreads();
#pragma unroll
        for (int i = 0; i < 4; i++)
            g_Wt[(c0 + ty + 8 * i) * DOUT + d0 + tx] = ts[tx][ty + 8 * i];
    } else {
        int e4 = (bx - 704) * 512 + t;
#pragma unroll
        for (int it = 0; it < 2; it++, e4 += 256) {
            int b = e4 >> 6;
            int p4 = e4 & 63;
            float4* dst = reinterpret_cast<float4*>(
                g_wsmall + (b * KALL + KREG) * PPIX + p4 * 4);
            *dst = make_float4(1.f, 1.f, 1.f, 1.f);
        }
    }
}

// ---------------------------------------------------------------------------
// K2 v2 (measured ~5.2us): per-batch GEMM
//   A[b] = (1/256) * w[20 x 256] * F[b]^T[256 x 384]
// ---------------------------------------------------------------------------
__global__ __launch_bounds__(256)
void k2_region_gemm(const float* __restrict__ F) {
    __shared__ float sm[10240];           // 40 KB
    float* ws = sm;                       // [p][k] 256*20 = 5120 floats
    float* fs = sm + 5120;                // [32 p][130] = 4160 floats
    float2* red = reinterpret_cast<float2*>(sm);  // [4][1280] float2 (reuse)

    int b = blockIdx.x;
    int c0 = blockIdx.y * 128;
    int t = threadIdx.x;
    int pg = t >> 6;
    int cgp = t & 63;

    const float* wsm = g_wsmall + b * KALL * PPIX;
    for (int idx = t; idx < KALL * PPIX; idx += 256) {
        int k = idx >> 8, p = idx & 255;
        ws[p * KALL + k] = wsm[idx];
    }

    const float* Fb = F + ((size_t)b * CCH + c0) * PPIX;

    float4 pf[4];
#pragma unroll
    for (int r = 0; r < 4; r++) {
        int linear = r * 256 + t;
        int c = linear >> 3;
        int p4 = linear & 7;
        pf[r] = *reinterpret_cast<const float4*>(Fb + c * PPIX + p4 * 4);
    }

    ull acc[10][2];
#pragma unroll
    for (int i = 0; i < 10; i++) { acc[i][0] = 0ull; acc[i][1] = 0ull; }

    for (int ch = 0; ch < 8; ch++) {
        if (ch) __syncthreads();
#pragma unroll
        for (int r = 0; r < 4; r++) {
            int linear = r * 256 + t;
            int c = linear >> 3;
            int p4 = linear & 7;
            fs[(p4 * 4 + 0) * 130 + c] = pf[r].x;
            fs[(p4 * 4 + 1) * 130 + c] = pf[r].y;
            fs[(p4 * 4 + 2) * 130 + c] = pf[r].z;
            fs[(p4 * 4 + 3) * 130 + c] = pf[r].w;
        }
        __syncthreads();
        if (ch < 7) {
#pragma unroll
            for (int r = 0; r < 4; r++) {
                int linear = r * 256 + t;
                int c = linear >> 3;
                int p4 = linear & 7;
                pf[r] = *reinterpret_cast<const float4*>(
                    Fb + c * PPIX + (ch + 1) * 32 + p4 * 4);
            }
        }

        int pc = ch * 32;
#pragma unroll
        for (int pp = 0; pp < 8; pp++) {
            int pl = pg * 8 + pp;
            const float* wr = ws + (pc + pl) * KALL;
            ull f2 = *reinterpret_cast<const ull*>(fs + pl * 130 + 2 * cgp);
            float f0, f1;
            unpack2(f2, f0, f1);
            ull fd0 = pack2(f0, f0);
            ull fd1 = pack2(f1, f1);
#pragma unroll
            for (int ki = 0; ki < 10; ki++) {
                ull w2 = *reinterpret_cast<const ull*>(wr + 2 * ki);
                acc[ki][0] = ffma2(w2, fd0, acc[ki][0]);
                acc[ki][1] = ffma2(w2, fd1, acc[ki][1]);
            }
        }
    }

    __syncthreads();
#pragma unroll
    for (int ki = 0; ki < 10; ki++) {
#pragma unroll
        for (int cc = 0; cc < 2; cc++) {
            float lo, hi;
            unpack2(acc[ki][cc], lo, hi);
            red[pg * 1280 + ki * 128 + 2 * cgp + cc] = make_float2(lo, hi);
        }
    }
    __syncthreads();

    const float inv = 1.0f / 256.0f;
    float* A = g_allfeats + (size_t)(b * KALL) * CCH + c0;
#pragma unroll
    for (int j = 0; j < 5; j++) {
        int i = t + 256 * j;
        float2 s0 = red[i];
        float2 s1 = red[1280 + i];
        float2 s2 = red[2560 + i];
        float2 s3 = red[3840 + i];
        float lo = (s0.x + s1.x) + (s2.x + s3.x);
        float hi = (s0.y + s1.y) + (s2.y + s3.y);
        int kp = i >> 7;
        int col = i & 127;
        A[(2 * kp) * CCH + col]     = lo * inv;
        A[(2 * kp + 1) * CCH + col] = hi * inv;
    }
}

// ---------------------------------------------------------------------------
// K3 v6: projection as an EXACT k2v2 mirror (20 FFMA2 per reduction step).
//   out[1280 x 256] = relu(A[1280 x 384] * Wt[384 x 256] + bias)
//  grid (64 rowgroups of 20, 2 d-halves of 128), 256 threads.
//  4 k-groups x 64 d-pair threads; thread: 10 row-pairs x 1 d-pair over its
//  96 k's. Per step: 1 spread LDS.64(w) + 10 broadcast LDS.64(a) + 20 FFMA2.
//  A staged [k][r=20] (same scatter as k2's ws). Register-prefetch Wt chunks;
//  4-way k-split tree reduce; bias+relu fused.
// ---------------------------------------------------------------------------
__global__ __launch_bounds__(256)
void k3_project(const float* __restrict__ bias, float* __restrict__ out) {
    __shared__ float sm[11904];           // 46.5 KB
    float* as = sm;                       // [k=384][r=20] = 7680 floats
    float* fs = sm + 7680;                // [32 k][132] = 4224 floats
    float2* red = reinterpret_cast<float2*>(sm);  // [4][1280] float2 (reuse)

    int t = threadIdx.x;
    int g = t >> 6;                       // k-group 0..3
    int dp = t & 63;                      // d-pair: d = d0 + 2dp + {0,1}
    int row0 = blockIdx.x * 20;
    int d0 = blockIdx.y * 128;

    const float* Wb = g_Wt + d0;

    // prefetch Wt chunk 0 (32 k x 128 d = 1024 float4, 4/thread)
    float4 pf[4];
#pragma unroll
    for (int i = 0; i < 4; i++) {
        int linear = i * 256 + t;
        int k = linear >> 5;              // 32 f4 per k-row
        int c4 = linear & 31;
        pf[i] = *reinterpret_cast<const float4*>(Wb + (size_t)k * DOUT + c4 * 4);
    }

    // stage A transposed: as[k*20 + r] = A[row0+r][k]   (20*384 = 7680)
    const float* Ar = g_allfeats + (size_t)row0 * CCH;
#pragma unroll
    for (int i = 0; i < 30; i++) {
        int idx = i * 256 + t;
        int r = idx / CCH;
        int k = idx - r * CCH;
        as[k * 20 + r] = Ar[idx];
    }

    ull acc[10][2];
#pragma unroll
    for (int i = 0; i < 10; i++) { acc[i][0] = 0ull; acc[i][1] = 0ull; }

    for (int ch = 0; ch < 12; ch++) {
        if (ch) __syncthreads();          // prior chunk's reads complete
#pragma unroll
        for (int i = 0; i < 4; i++) {
            int linear = i * 256 + t;
            int k = linear >> 5;
            int c4 = linear & 31;
            *reinterpret_cast<float4*>(fs + k * 132 + c4 * 4) = pf[i];
        }
        __syncthreads();                  // fs (and as on ch=0) visible
        if (ch < 11) {
#pragma unroll
            for (int i = 0; i < 4; i++) {
                int linear = i * 256 + t;
                int k = linear >> 5;
                int c4 = linear & 31;
                pf[i] = *reinterpret_cast<const float4*>(
                    Wb + (size_t)((ch + 1) * 32 + k) * DOUT + c4 * 4);
            }
        }

        int kbase = ch * 32;
#pragma unroll
        for (int j = 0; j < 8; j++) {
            int kk = g * 8 + j;           // k within chunk
            const float* arow = as + (kbase + kk) * 20;
            ull w2 = *reinterpret_cast<const ull*>(fs + kk * 132 + 2 * dp);
            float w0, w1;
            unpack2(w2, w0, w1);
            ull wd0 = pack2(w0, w0);
            ull wd1 = pack2(w1, w1);
#pragma unroll
            for (int ri = 0; ri < 10; ri++) {
                ull a2 = *reinterpret_cast<const ull*>(arow + 2 * ri);  // broadcast
                acc[ri][0] = ffma2(a2, wd0, acc[ri][0]);
                acc[ri][1] = ffma2(a2, wd1, acc[ri][1]);
            }
        }
    }

    // tree reduce over 4 k-groups (red overlays as/fs)
    __syncthreads();
#pragma unroll
    for (int ri = 0; ri < 10; ri++) {
#pragma unroll
        for (int cc = 0; cc < 2; cc++) {
            float lo, hi;
            unpack2(acc[ri][cc], lo, hi);
            red[g * 1280 + dp * 20 + ri * 2 + cc] = make_float2(lo, hi);
        }
    }
    __syncthreads();

#pragma unroll
    for (int j = 0; j < 5; j++) {
        int idx = j * 256 + t;            // 0..1279
        float2 s0 = red[idx];
        float2 s1 = red[1280 + idx];
        float2 s2 = red[2560 + idx];
        float2 s3 = red[3840 + idx];
        float lo = (s0.x + s1.x) + (s2.x + s3.x);
        float hi = (s0.y + s1.y) + (s2.y + s3.y);
        int dpi = idx / 20;
        int rem = idx - dpi * 20;
        int ri = rem >> 1;
        int cc = rem & 1;
        int d = d0 + 2 * dpi + cc;
        float bv = bias[d];
        out[(size_t)(row0 + 2 * ri) * DOUT + d]     = fmaxf(lo + bv, 0.0f);
        out[(size_t)(row0 + 2 * ri + 1) * DOUT + d] = fmaxf(hi + bv, 0.0f);
    }
}

// ---------------------------------------------------------------------------
extern "C" void kernel_launch(void* const* d_in, const int* in_sizes, int n_in,
                              void* d_out, int out_size) {
    const float* F    = (const float*)d_in[0];   // [64,384,16,16]
    const float* seg  = (const float*)d_in[1];   // [64,19,256,256]
    const float* W    = (const float*)d_in[2];   // [256,384]
    const float* bias = (const float*)d_in[3];   // [256]
    float* out = (float*)d_out;                  // [64, 5120]

    kA_prep<<<712, 256>>>(seg, W);
    k2_region_gemm<<<dim3(BSZ, 3), 256>>>(F);
    k3_project<<<dim3(64, 2), 256>>>(bias, out);
}